// round 16
// baseline (speedup 1.0000x reference)
#include <cuda_runtime.h>
#include <cuda_bf16.h>
#include <cstdint>

#define BB 8192
#define II 128
#define HH 2048
#define N3 4096
#define NCHUNK 18
#define CHLEN 7

// Static scratch (allocation-free)
__device__ __nv_bfloat16 g_xb[BB * II];
__device__ __nv_bfloat16 g_W0b[HH * II];
__device__ __nv_bfloat16 g_W1b[(size_t)HH * HH];
__device__ __nv_bfloat16 g_W2b[(size_t)HH * HH];
__device__ __nv_bfloat16 g_W3b[(size_t)N3 * HH];
__device__ __nv_bfloat16 g_h0[(size_t)BB * HH];
__device__ __nv_bfloat16 g_h1[(size_t)BB * HH];
__device__ float g_lp[(size_t)II * BB * 16];
__device__ float g_cm[NCHUNK * BB * 16];
__device__ float g_cs[NCHUNK * BB];

// ---------------------------------------------------------------------------
// Degree-sort permutation (analytic). Hidden degrees d = n % 127 over H=2048:
// degrees 0..15 appear 17x, 16..126 appear 16x.
__host__ __device__ __forceinline__ int pdeg(int s) { return (s < 272) ? (s / 17) : ((s - 16) >> 4); }
__host__ __device__ __forceinline__ int cumdeg(int d) { return (d < 16) ? (17 * d) : (16 * d + 16); }
__host__ __device__ __forceinline__ int pmap(int s) {
    int d = pdeg(s);
    int j = s - cumdeg(d);
    return d + 127 * j;
}

// ---------------------------------------------------------------------------
// Prologue part 1 (main stream): x->bf16 + W0 masked/permuted.
__global__ __launch_bounds__(256) void pro_xw0_k(
    const float* __restrict__ x, const float* __restrict__ W0)
{
    int bid = blockIdx.x;
    const int tid = threadIdx.x;

    if (bid < 1024) {  // x -> bf16
        int i = bid * 256 + tid;
        float4 v = ((const float4*)x)[i];
        ((__nv_bfloat162*)g_xb)[i * 2 + 0] = __floats2bfloat162_rn(v.x, v.y);
        ((__nv_bfloat162*)g_xb)[i * 2 + 1] = __floats2bfloat162_rn(v.z, v.w);
        return;
    }
    bid -= 1024;       // [0,256): W0 rows permuted, cols natural; mask pdeg(n') >= k
    int idx = bid * 256 + tid;      // n' * 32 + chunk-of-4
    int n = idx >> 5;
    int k0 = (idx & 31) * 4;
    int nd = pdeg(n);
    const float* src = W0 + (size_t)pmap(n) * II + k0;
    float f[4] = {src[0], src[1], src[2], src[3]};
#pragma unroll
    for (int j = 0; j < 4; j++)
        if (nd < k0 + j) f[j] = 0.f;
    ((__nv_bfloat162*)g_W0b)[idx * 2 + 0] = __floats2bfloat162_rn(f[0], f[1]);
    ((__nv_bfloat162*)g_W0b)[idx * 2 + 1] = __floats2bfloat162_rn(f[2], f[3]);
}

// Prologue part 2 (side stream): one weight matrix, masked/permuted, trimmed.
// MT=1: rows+cols permuted, mask pdeg(n') >= pdeg(k').
// MT=2: rows natural, cols permuted, mask (n>>5)-1 >= pdeg(k').
template <int MT>
__global__ __launch_bounds__(256) void pro_w_k(
    const float* __restrict__ W, __nv_bfloat16* __restrict__ Wb)
{
    __shared__ float row[HH];
    const int n = blockIdx.x;
    const int tid = threadIdx.x;
    int thresh, srcn, kmaxb;
    if (MT == 1) { thresh = pdeg(n); srcn = pmap(n); kmaxb = cumdeg(pdeg(n | 63) + 1); }
    else         { thresh = (n >> 5) - 1; srcn = n;  kmaxb = cumdeg(min((n | 63) >> 5, 127)); }
    int wlen = (kmaxb + 63) & ~63;
    if (wlen < 64) wlen = 64;
    if (wlen > HH) wlen = HH;

    const float* Wr = W + (size_t)srcn * HH;
    for (int k = tid; k < HH / 4; k += 256)
        *(float4*)(row + 4 * k) = ((const float4*)Wr)[k];
    __syncthreads();
    __nv_bfloat162* dst = (__nv_bfloat162*)(Wb + (size_t)n * HH);
    for (int k2 = tid; k2 < wlen / 2; k2 += 256) {
        int ka = 2 * k2, kb = 2 * k2 + 1;
        float va = (pdeg(ka) <= thresh) ? row[pmap(ka)] : 0.f;
        float vb = (pdeg(kb) <= thresh) ? row[pmap(kb)] : 0.f;
        dst[k2] = __floats2bfloat162_rn(va, vb);
    }
}

// ---------------------------------------------------------------------------
__device__ __forceinline__ void cp16(void* s, const void* g) {
    uint32_t sa = (uint32_t)__cvta_generic_to_shared(s);
    asm volatile("cp.async.cg.shared.global [%0], [%1], 16;\n" :: "r"(sa), "l"(g));
}
__device__ __forceinline__ void cp_commit() { asm volatile("cp.async.commit_group;\n"); }
template <int N_>
__device__ __forceinline__ void cp_wait() { asm volatile("cp.async.wait_group %0;\n" :: "n"(N_)); }

__device__ __forceinline__ void ldsm4(uint32_t* r, const __nv_bfloat16* p) {
    uint32_t a = (uint32_t)__cvta_generic_to_shared(p);
    asm volatile("ldmatrix.sync.aligned.m8n8.x4.shared.b16 {%0,%1,%2,%3}, [%4];"
                 : "=r"(r[0]), "=r"(r[1]), "=r"(r[2]), "=r"(r[3]) : "r"(a));
}

__device__ __forceinline__ void mma_bf16(float* c, const uint32_t* a, const uint32_t* b) {
    asm volatile(
        "mma.sync.aligned.m16n8k16.row.col.f32.bf16.bf16.f32 "
        "{%0,%1,%2,%3}, {%4,%5,%6,%7}, {%8,%9}, {%0,%1,%2,%3};"
        : "+f"(c[0]), "+f"(c[1]), "+f"(c[2]), "+f"(c[3])
        : "r"(a[0]), "r"(a[1]), "r"(a[2]), "r"(a[3]), "r"(b[0]), "r"(b[1]));
}

// ---------------------------------------------------------------------------
// bf16 GEMM: identical to the converged R15 kernel (peeled k-tail, template K).
template <int MT, int EPI, int KT>
__global__ __launch_bounds__(128, 4)
void gemm_bf16_k(const __nv_bfloat16* __restrict__ A, const __nv_bfloat16* __restrict__ W,
                 const float* __restrict__ bias, float* __restrict__ outf,
                 __nv_bfloat16* __restrict__ outb, const float* __restrict__ xin,
                 int N)
{
    extern __shared__ __nv_bfloat16 sm[];
    __nv_bfloat16* As = sm;                    // [2][128*64]
    __nv_bfloat16* Bs = sm + 2 * 128 * 64;     // [2][64*64]

    const int tid = threadIdx.x;
    const int lane = tid & 31;
    const int warp = tid >> 5;
    const int wM = warp & 1;
    const int wN = warp >> 1;
    const int q = lane & 3;
    const int g = lane >> 2;
    const int rb = blockIdx.x * 128;
    const int cbi = gridDim.y - 1 - blockIdx.y;
    const int cb = cbi * 64;

    int kmax;
    if (MT == 0)      kmax = pdeg(cb + 63) + 1;
    else if (MT == 1) kmax = cumdeg(pdeg(cb + 63) + 1);
    else              kmax = cumdeg(min(((cb + 63) >> 5), 127));
    const int nk = KT >> 6;
    int nkEff = (kmax + 63) >> 6;
    if (nkEff < 1) nkEff = 1;
    if (nkEff > nk) nkEff = nk;
    int ksTail = (kmax - ((nkEff - 1) << 6) + 15) >> 4;
    if (ksTail < 1) ksTail = 1;
    if (ksTail > 4) ksTail = 4;

    float acc[4][4][4];
#pragma unroll
    for (int mt = 0; mt < 4; mt++)
#pragma unroll
        for (int nt = 0; nt < 4; nt++)
#pragma unroll
            for (int e = 0; e < 4; e++) acc[mt][nt][e] = 0.f;

    const __nv_bfloat16* Ab = A + (size_t)rb * KT;
    const __nv_bfloat16* Wb = W + (size_t)cb * KT;

    const int sr = tid >> 3;
    const int sc = tid & 7;

    // stage tile 0 into buffer 0
    {
#pragma unroll
        for (int it = 0; it < 8; it++) {
            int row = it * 16 + sr;
            int pc = sc ^ (row & 7);
            cp16(&As[row * 64 + pc * 8], Ab + (size_t)row * KT + sc * 8);
        }
#pragma unroll
        for (int it = 0; it < 4; it++) {
            int row = it * 16 + sr;
            int pc = sc ^ (row & 7);
            cp16(&Bs[row * 64 + pc * 8], Wb + (size_t)row * KT + sc * 8);
        }
        cp_commit();
    }

    const int l7 = lane & 7;
    const int aRowOff = ((lane >> 3) & 1) << 3;
    const int aChOff = lane >> 4;
    const int bRowOff = (lane >> 4) << 3;
    const int bChOff = (lane >> 3) & 1;

    int cur = 0;
    // main loop: nkEff-1 full tiles, branch-free body
    for (int kt = 0; kt < nkEff - 1; kt++) {
        cp_wait<0>();
        __syncthreads();

        {
            const int ko = (kt + 1) * 64;
            const int aob = (cur ^ 1) * 128 * 64;
            const int bob = (cur ^ 1) * 64 * 64;
#pragma unroll
            for (int it = 0; it < 8; it++) {
                int row = it * 16 + sr;
                int pc = sc ^ (row & 7);
                cp16(&As[aob + row * 64 + pc * 8], Ab + (size_t)row * KT + ko + sc * 8);
            }
#pragma unroll
            for (int it = 0; it < 4; it++) {
                int row = it * 16 + sr;
                int pc = sc ^ (row & 7);
                cp16(&Bs[bob + row * 64 + pc * 8], Wb + (size_t)row * KT + ko + sc * 8);
            }
            cp_commit();
        }

        const __nv_bfloat16* sA = As + cur * 128 * 64;
        const __nv_bfloat16* sB = Bs + cur * 64 * 64;
#pragma unroll
        for (int ks = 0; ks < 4; ks++) {
            uint32_t af[4][4], bf[2][4];
#pragma unroll
            for (int mt = 0; mt < 4; mt++) {
                int row = wM * 64 + mt * 16 + aRowOff + l7;
                int ch = ks * 2 + aChOff;
                ldsm4(af[mt], sA + row * 64 + ((ch ^ (row & 7)) << 3));
            }
#pragma unroll
            for (int ntp = 0; ntp < 2; ntp++) {
                int row = wN * 32 + ntp * 16 + bRowOff + l7;
                int ch = ks * 2 + bChOff;
                ldsm4(bf[ntp], sB + row * 64 + ((ch ^ (row & 7)) << 3));
            }
#pragma unroll
            for (int mt = 0; mt < 4; mt++)
#pragma unroll
                for (int nt = 0; nt < 4; nt++)
                    mma_bf16(acc[mt][nt], af[mt], &bf[nt >> 1][(nt & 1) * 2]);
        }

        cur ^= 1;
    }

    // peeled final tile: runtime ks bound
    {
        cp_wait<0>();
        __syncthreads();
        const __nv_bfloat16* sA = As + cur * 128 * 64;
        const __nv_bfloat16* sB = Bs + cur * 64 * 64;
#pragma unroll 1
        for (int ks = 0; ks < ksTail; ks++) {
            uint32_t af[4][4], bf[2][4];
#pragma unroll
            for (int mt = 0; mt < 4; mt++) {
                int row = wM * 64 + mt * 16 + aRowOff + l7;
                int ch = ks * 2 + aChOff;
                ldsm4(af[mt], sA + row * 64 + ((ch ^ (row & 7)) << 3));
            }
#pragma unroll
            for (int ntp = 0; ntp < 2; ntp++) {
                int row = wN * 32 + ntp * 16 + bRowOff + l7;
                int ch = ks * 2 + bChOff;
                ldsm4(bf[ntp], sB + row * 64 + ((ch ^ (row & 7)) << 3));
            }
#pragma unroll
            for (int mt = 0; mt < 4; mt++)
#pragma unroll
                for (int nt = 0; nt < 4; nt++)
                    mma_bf16(acc[mt][nt], af[mt], &bf[nt >> 1][(nt & 1) * 2]);
        }
    }

    if (EPI == 0) {
#pragma unroll
        for (int mt = 0; mt < 4; mt++)
#pragma unroll
            for (int hh = 0; hh < 2; hh++) {
                int r = rb + wM * 64 + mt * 16 + hh * 8 + g;
#pragma unroll
                for (int nt = 0; nt < 4; nt++) {
                    int cn = cb + wN * 32 + nt * 8 + 2 * q;
                    float v0 = fmaxf(acc[mt][nt][hh * 2 + 0] + __ldg(&bias[pmap(cn)]), 0.f);
                    float v1 = fmaxf(acc[mt][nt][hh * 2 + 1] + __ldg(&bias[pmap(cn + 1)]), 0.f);
                    *(__nv_bfloat162*)(outb + (size_t)r * N + cn) = __floats2bfloat162_rn(v0, v1);
                }
            }
    } else {
        const float CNORM = 2.3052328943245633f;  // 0.5*ln(2pi) + ln(4)
        const int ii = (cb + wN * 32) >> 5;
#pragma unroll
        for (int mt = 0; mt < 4; mt++)
#pragma unroll
            for (int hh = 0; hh < 2; hh++) {
                int r = rb + wM * 64 + mt * 16 + hh * 8 + g;
                float xv = xin[(size_t)r * II + ii];
#pragma unroll
                for (int nt = 0; nt < 2; nt++) {
                    int colm = cb + wN * 32 + nt * 8 + 2 * q;
                    float lp[2];
#pragma unroll
                    for (int e = 0; e < 2; e++) {
                        float mu = acc[mt][nt][hh * 2 + e] + bias[colm + e];
                        float al = acc[mt][nt + 2][hh * 2 + e] + bias[colm + 16 + e];
                        float t = (xv - mu) * __expf(-al);
                        lp[e] = -0.5f * t * t - al - CNORM;
                    }
                    int a = nt * 8 + 2 * q;
                    *(float2*)(outf + ((size_t)ii * BB + r) * 16 + a) = make_float2(lp[0], lp[1]);
                }
            }
    }
}

// ---------------------------------------------------------------------------
__device__ __forceinline__ float max16(const float* v) {
    float m = v[0];
#pragma unroll
    for (int i = 1; i < 16; i++) m = fmaxf(m, v[i]);
    return m;
}

__device__ __forceinline__ void load16(float* d, const float* src) {
    const float4* p = (const float4*)src;
    float4 v0 = p[0], v1 = p[1], v2 = p[2], v3 = p[3];
    d[0] = v0.x; d[1] = v0.y; d[2] = v0.z;  d[3] = v0.w;
    d[4] = v1.x; d[5] = v1.y; d[6] = v1.z;  d[7] = v1.w;
    d[8] = v2.x; d[9] = v2.y; d[10] = v2.z; d[11] = v2.w;
    d[12] = v3.x; d[13] = v3.y; d[14] = v3.z; d[15] = v3.w;
}

__device__ __forceinline__ void matmul44(float* Mn, const float* M, const float* E) {
#pragma unroll
    for (int r = 0; r < 4; r++)
#pragma unroll
        for (int j = 0; j < 4; j++) {
            float s = M[r * 4 + 0] * E[j];
            s = fmaf(M[r * 4 + 1], E[4 + j], s);
            s = fmaf(M[r * 4 + 2], E[8 + j], s);
            s = fmaf(M[r * 4 + 3], E[12 + j], s);
            Mn[r * 4 + j] = s;
        }
}

__global__ __launch_bounds__(256) void chainA_k()
{
    const int b = blockIdx.x * 256 + threadIdx.x;
    const int c = blockIdx.y;
    const int i0 = 1 + c * CHLEN;

    float M[16], S;
    {
        float lp[16];
        load16(lp, g_lp + ((size_t)i0 * BB + b) * 16);
        float mx = max16(lp);
        S = mx;
#pragma unroll
        for (int a = 0; a < 16; a++) M[a] = __expf(lp[a] - mx);
    }
#pragma unroll
    for (int s = 1; s < CHLEN; s++) {
        float lp[16];
        load16(lp, g_lp + ((size_t)(i0 + s) * BB + b) * 16);
        float mx = max16(lp);
        float E[16];
#pragma unroll
        for (int a = 0; a < 16; a++) E[a] = __expf(lp[a] - mx);
        float Mn[16];
        matmul44(Mn, M, E);
        float nm = fmaxf(max16(Mn), 1e-30f);
        float inv = 1.0f / nm;
#pragma unroll
        for (int a = 0; a < 16; a++) M[a] = Mn[a] * inv;
        S += mx + __logf(nm);
    }
    float4* o = (float4*)(g_cm + ((size_t)c * BB + b) * 16);
    o[0] = make_float4(M[0], M[1], M[2], M[3]);
    o[1] = make_float4(M[4], M[5], M[6], M[7]);
    o[2] = make_float4(M[8], M[9], M[10], M[11]);
    o[3] = make_float4(M[12], M[13], M[14], M[15]);
    g_cs[c * BB + b] = S;
}

__global__ __launch_bounds__(256) void chainB_k(float* __restrict__ out)
{
    const int b = blockIdx.x * 256 + threadIdx.x;

    float M[16];
    load16(M, g_cm + (size_t)b * 16);
    float S = g_cs[b];

    for (int c = 1; c < NCHUNK; c++) {
        float E[16];
        load16(E, g_cm + ((size_t)c * BB + b) * 16);
        float Mn[16];
        matmul44(Mn, M, E);
        float nm = fmaxf(max16(Mn), 1e-30f);
        float inv = 1.0f / nm;
#pragma unroll
        for (int a = 0; a < 16; a++) M[a] = Mn[a] * inv;
        S += g_cs[c * BB + b] + __logf(nm);
    }

    const float* lp0 = g_lp + (size_t)b * 16;
    const float* lpL = g_lp + ((size_t)127 * BB + b) * 16;
    float f[4] = {lp0[0], lp0[1], lp0[2], lp0[3]};
    float l[4] = {lpL[0], lpL[4], lpL[8], lpL[12]};
    float fm = fmaxf(fmaxf(f[0], f[1]), fmaxf(f[2], f[3]));
    float lm = fmaxf(fmaxf(l[0], l[1]), fmaxf(l[2], l[3]));
    float ef[4], el[4];
#pragma unroll
    for (int i = 0; i < 4; i++) { ef[i] = __expf(f[i] - fm); el[i] = __expf(l[i] - lm); }
    float acc = 0.f;
#pragma unroll
    for (int i = 0; i < 4; i++) {
        float rs = M[i * 4 + 0] * el[0];
        rs = fmaf(M[i * 4 + 1], el[1], rs);
        rs = fmaf(M[i * 4 + 2], el[2], rs);
        rs = fmaf(M[i * 4 + 3], el[3], rs);
        acc = fmaf(ef[i], rs, acc);
    }
    out[b] = S + fm + lm + __logf(acc);
}

// ---------------------------------------------------------------------------
extern "C" void kernel_launch(void* const* d_in, const int* in_sizes, int n_in,
                              void* d_out, int out_size)
{
    const float* x  = (const float*)d_in[0];
    const float* W0 = (const float*)d_in[1];
    const float* b0 = (const float*)d_in[2];
    const float* W1 = (const float*)d_in[3];
    const float* b1 = (const float*)d_in[4];
    const float* W2 = (const float*)d_in[5];
    const float* b2 = (const float*)d_in[6];
    const float* W3 = (const float*)d_in[7];
    const float* b3 = (const float*)d_in[8];

    __nv_bfloat16 *xb, *W0b, *W1b, *W2b, *W3b, *h0, *h1;
    float* lp;
    cudaGetSymbolAddress((void**)&xb, g_xb);
    cudaGetSymbolAddress((void**)&W0b, g_W0b);
    cudaGetSymbolAddress((void**)&W1b, g_W1b);
    cudaGetSymbolAddress((void**)&W2b, g_W2b);
    cudaGetSymbolAddress((void**)&W3b, g_W3b);
    cudaGetSymbolAddress((void**)&h0, g_h0);
    cudaGetSymbolAddress((void**)&h1, g_h1);
    cudaGetSymbolAddress((void**)&lp, g_lp);

    // one-time handles (created on the first, uncaptured call; identical
    // work is enqueued on every call)
    static cudaStream_t s2 = nullptr;
    static cudaEvent_t evRoot = nullptr, ev1 = nullptr, ev2 = nullptr, ev3 = nullptr;
    if (!s2) {
        cudaStreamCreateWithFlags(&s2, cudaStreamNonBlocking);
        cudaEventCreateWithFlags(&evRoot, cudaEventDisableTiming);
        cudaEventCreateWithFlags(&ev1, cudaEventDisableTiming);
        cudaEventCreateWithFlags(&ev2, cudaEventDisableTiming);
        cudaEventCreateWithFlags(&ev3, cudaEventDisableTiming);
    }

    // 2 stages x (A 16KB + B 8KB) = 48KB
    const int SMEM = 2 * (128 * 64 + 64 * 64) * (int)sizeof(__nv_bfloat16);
    cudaFuncSetAttribute(gemm_bf16_k<0, 0, II>, cudaFuncAttributeMaxDynamicSharedMemorySize, SMEM);
    cudaFuncSetAttribute(gemm_bf16_k<1, 0, HH>, cudaFuncAttributeMaxDynamicSharedMemorySize, SMEM);
    cudaFuncSetAttribute(gemm_bf16_k<2, 1, HH>, cudaFuncAttributeMaxDynamicSharedMemorySize, SMEM);

    // fork: weight conversions W1/W2/W3 on side stream, overlapped with GEMMs
    cudaEventRecord(evRoot, 0);
    cudaStreamWaitEvent(s2, evRoot, 0);
    pro_w_k<1><<<HH, 256, 0, s2>>>(W1, W1b);
    cudaEventRecord(ev1, s2);
    pro_w_k<1><<<HH, 256, 0, s2>>>(W2, W2b);
    cudaEventRecord(ev2, s2);
    pro_w_k<2><<<N3, 256, 0, s2>>>(W3, W3b);
    cudaEventRecord(ev3, s2);

    // main stream: x+W0, then GEMMs joining each weight event just-in-time
    pro_xw0_k<<<1280, 256>>>(x, W0);
    gemm_bf16_k<0, 0, II><<<dim3(BB / 128, HH / 64), 128, SMEM>>>(xb, W0b, b0, nullptr, h0, nullptr, HH);
    cudaStreamWaitEvent(0, ev1, 0);
    gemm_bf16_k<1, 0, HH><<<dim3(BB / 128, HH / 64), 128, SMEM>>>(h0, W1b, b1, nullptr, h1, nullptr, HH);
    cudaStreamWaitEvent(0, ev2, 0);
    gemm_bf16_k<1, 0, HH><<<dim3(BB / 128, HH / 64), 128, SMEM>>>(h1, W2b, b2, nullptr, h0, nullptr, HH);
    cudaStreamWaitEvent(0, ev3, 0);
    gemm_bf16_k<2, 1, HH><<<dim3(BB / 128, N3 / 64), 128, SMEM>>>(h0, W3b, b3, lp, nullptr, x, N3);

    // chain
    chainA_k<<<dim3(BB / 256, NCHUNK), 256>>>();
    chainB_k<<<BB / 256, 256>>>((float*)d_out);
}

// round 17
// speedup vs baseline: 1.0434x; 1.0434x over previous
#include <cuda_runtime.h>
#include <cuda_bf16.h>
#include <cstdint>

#define BB 8192
#define II 128
#define HH 2048
#define N3 4096
#define NCHUNK 18
#define CHLEN 7

// Static scratch (allocation-free)
__device__ __nv_bfloat16 g_xb[BB * II];
__device__ __nv_bfloat16 g_W0b[HH * II];
__device__ __nv_bfloat16 g_W1b[(size_t)HH * HH];
__device__ __nv_bfloat16 g_W2b[(size_t)HH * HH];
__device__ __nv_bfloat16 g_W3b[(size_t)N3 * HH];
__device__ __nv_bfloat16 g_h0[(size_t)BB * HH];
__device__ __nv_bfloat16 g_h1[(size_t)BB * HH];
__device__ float g_b0p[HH];
__device__ float g_b1p[HH];
__device__ float g_b2p[HH];
__device__ float g_lp[(size_t)II * BB * 16];
__device__ float g_cm[NCHUNK * BB * 16];
__device__ float g_cs[NCHUNK * BB];

// ---------------------------------------------------------------------------
// Degree-sort permutation (analytic). Hidden degrees d = n % 127 over H=2048:
// degrees 0..15 appear 17x, 16..126 appear 16x.
__host__ __device__ __forceinline__ int pdeg(int s) { return (s < 272) ? (s / 17) : ((s - 16) >> 4); }
__host__ __device__ __forceinline__ int cumdeg(int d) { return (d < 16) ? (17 * d) : (16 * d + 16); }
__host__ __device__ __forceinline__ int pmap(int s) {
    int d = pdeg(s);
    int j = s - cumdeg(d);
    return d + 127 * j;
}

// ---------------------------------------------------------------------------
// Prologue part 1 (main stream): x->bf16 + W0 masked/permuted + permuted biases.
__global__ __launch_bounds__(256) void pro_xw0_k(
    const float* __restrict__ x, const float* __restrict__ W0,
    const float* __restrict__ b0, const float* __restrict__ b1,
    const float* __restrict__ b2)
{
    int bid = blockIdx.x;
    const int tid = threadIdx.x;

    if (bid < 1024) {  // x -> bf16
        int i = bid * 256 + tid;
        float4 v = ((const float4*)x)[i];
        ((__nv_bfloat162*)g_xb)[i * 2 + 0] = __floats2bfloat162_rn(v.x, v.y);
        ((__nv_bfloat162*)g_xb)[i * 2 + 1] = __floats2bfloat162_rn(v.z, v.w);
        return;
    }
    bid -= 1024;
    if (bid < 256) {   // W0 rows permuted, cols natural; mask pdeg(n') >= k
        int idx = bid * 256 + tid;      // n' * 32 + chunk-of-4
        int n = idx >> 5;
        int k0 = (idx & 31) * 4;
        int nd = pdeg(n);
        const float* src = W0 + (size_t)pmap(n) * II + k0;
        float f[4] = {src[0], src[1], src[2], src[3]};
#pragma unroll
        for (int j = 0; j < 4; j++)
            if (nd < k0 + j) f[j] = 0.f;
        ((__nv_bfloat162*)g_W0b)[idx * 2 + 0] = __floats2bfloat162_rn(f[0], f[1]);
        ((__nv_bfloat162*)g_W0b)[idx * 2 + 1] = __floats2bfloat162_rn(f[2], f[3]);
        return;
    }
    bid -= 256;        // [0,24): permuted biases (exact fp32 copies)
    int i = (bid % 8) * 256 + tid;
    int p = pmap(i);
    if (bid < 8)       g_b0p[i] = b0[p];
    else if (bid < 16) g_b1p[i] = b1[p];
    else               g_b2p[i] = b2[p];
}

// Prologue part 2 (side stream): one weight matrix, masked/permuted, trimmed.
// MT=1: rows+cols permuted, mask pdeg(n') >= pdeg(k').
// MT=2: rows natural, cols permuted, mask (n>>5)-1 >= pdeg(k').
template <int MT>
__global__ __launch_bounds__(256) void pro_w_k(
    const float* __restrict__ W, __nv_bfloat16* __restrict__ Wb)
{
    __shared__ float row[HH];
    const int n = blockIdx.x;
    const int tid = threadIdx.x;
    int thresh, srcn, kmaxb;
    if (MT == 1) { thresh = pdeg(n); srcn = pmap(n); kmaxb = cumdeg(pdeg(n | 63) + 1); }
    else         { thresh = (n >> 5) - 1; srcn = n;  kmaxb = cumdeg(min((n | 63) >> 5, 127)); }
    int wlen = (kmaxb + 63) & ~63;
    if (wlen < 64) wlen = 64;
    if (wlen > HH) wlen = HH;

    const float* Wr = W + (size_t)srcn * HH;
    for (int k = tid; k < HH / 4; k += 256)
        *(float4*)(row + 4 * k) = ((const float4*)Wr)[k];
    __syncthreads();
    __nv_bfloat162* dst = (__nv_bfloat162*)(Wb + (size_t)n * HH);
    for (int k2 = tid; k2 < wlen / 2; k2 += 256) {
        int ka = 2 * k2, kb = 2 * k2 + 1;
        float va = (pdeg(ka) <= thresh) ? row[pmap(ka)] : 0.f;
        float vb = (pdeg(kb) <= thresh) ? row[pmap(kb)] : 0.f;
        dst[k2] = __floats2bfloat162_rn(va, vb);
    }
}

// ---------------------------------------------------------------------------
__device__ __forceinline__ void cp16(void* s, const void* g) {
    uint32_t sa = (uint32_t)__cvta_generic_to_shared(s);
    asm volatile("cp.async.cg.shared.global [%0], [%1], 16;\n" :: "r"(sa), "l"(g));
}
__device__ __forceinline__ void cp_commit() { asm volatile("cp.async.commit_group;\n"); }
template <int N_>
__device__ __forceinline__ void cp_wait() { asm volatile("cp.async.wait_group %0;\n" :: "n"(N_)); }

__device__ __forceinline__ void ldsm4(uint32_t* r, const __nv_bfloat16* p) {
    uint32_t a = (uint32_t)__cvta_generic_to_shared(p);
    asm volatile("ldmatrix.sync.aligned.m8n8.x4.shared.b16 {%0,%1,%2,%3}, [%4];"
                 : "=r"(r[0]), "=r"(r[1]), "=r"(r[2]), "=r"(r[3]) : "r"(a));
}

__device__ __forceinline__ void mma_bf16(float* c, const uint32_t* a, const uint32_t* b) {
    asm volatile(
        "mma.sync.aligned.m16n8k16.row.col.f32.bf16.bf16.f32 "
        "{%0,%1,%2,%3}, {%4,%5,%6,%7}, {%8,%9}, {%0,%1,%2,%3};"
        : "+f"(c[0]), "+f"(c[1]), "+f"(c[2]), "+f"(c[3])
        : "r"(a[0]), "r"(a[1]), "r"(a[2]), "r"(a[3]), "r"(b[0]), "r"(b[1]));
}

// ---------------------------------------------------------------------------
// bf16 GEMM: converged R15 kernel (peeled k-tail, template K). EPI=0 bias is
// now a pre-permuted array -> plain bias[cn] load (bit-identical math).
template <int MT, int EPI, int KT>
__global__ __launch_bounds__(128, 4)
void gemm_bf16_k(const __nv_bfloat16* __restrict__ A, const __nv_bfloat16* __restrict__ W,
                 const float* __restrict__ bias, float* __restrict__ outf,
                 __nv_bfloat16* __restrict__ outb, const float* __restrict__ xin,
                 int N)
{
    extern __shared__ __nv_bfloat16 sm[];
    __nv_bfloat16* As = sm;                    // [2][128*64]
    __nv_bfloat16* Bs = sm + 2 * 128 * 64;     // [2][64*64]

    const int tid = threadIdx.x;
    const int lane = tid & 31;
    const int warp = tid >> 5;
    const int wM = warp & 1;
    const int wN = warp >> 1;
    const int q = lane & 3;
    const int g = lane >> 2;
    const int rb = blockIdx.x * 128;
    const int cbi = gridDim.y - 1 - blockIdx.y;
    const int cb = cbi * 64;

    int kmax;
    if (MT == 0)      kmax = pdeg(cb + 63) + 1;
    else if (MT == 1) kmax = cumdeg(pdeg(cb + 63) + 1);
    else              kmax = cumdeg(min(((cb + 63) >> 5), 127));
    const int nk = KT >> 6;
    int nkEff = (kmax + 63) >> 6;
    if (nkEff < 1) nkEff = 1;
    if (nkEff > nk) nkEff = nk;
    int ksTail = (kmax - ((nkEff - 1) << 6) + 15) >> 4;
    if (ksTail < 1) ksTail = 1;
    if (ksTail > 4) ksTail = 4;

    float acc[4][4][4];
#pragma unroll
    for (int mt = 0; mt < 4; mt++)
#pragma unroll
        for (int nt = 0; nt < 4; nt++)
#pragma unroll
            for (int e = 0; e < 4; e++) acc[mt][nt][e] = 0.f;

    const __nv_bfloat16* Ab = A + (size_t)rb * KT;
    const __nv_bfloat16* Wb = W + (size_t)cb * KT;

    const int sr = tid >> 3;
    const int sc = tid & 7;

    // stage tile 0 into buffer 0
    {
#pragma unroll
        for (int it = 0; it < 8; it++) {
            int row = it * 16 + sr;
            int pc = sc ^ (row & 7);
            cp16(&As[row * 64 + pc * 8], Ab + (size_t)row * KT + sc * 8);
        }
#pragma unroll
        for (int it = 0; it < 4; it++) {
            int row = it * 16 + sr;
            int pc = sc ^ (row & 7);
            cp16(&Bs[row * 64 + pc * 8], Wb + (size_t)row * KT + sc * 8);
        }
        cp_commit();
    }

    const int l7 = lane & 7;
    const int aRowOff = ((lane >> 3) & 1) << 3;
    const int aChOff = lane >> 4;
    const int bRowOff = (lane >> 4) << 3;
    const int bChOff = (lane >> 3) & 1;

    int cur = 0;
    // main loop: nkEff-1 full tiles, branch-free body
    for (int kt = 0; kt < nkEff - 1; kt++) {
        cp_wait<0>();
        __syncthreads();

        {
            const int ko = (kt + 1) * 64;
            const int aob = (cur ^ 1) * 128 * 64;
            const int bob = (cur ^ 1) * 64 * 64;
#pragma unroll
            for (int it = 0; it < 8; it++) {
                int row = it * 16 + sr;
                int pc = sc ^ (row & 7);
                cp16(&As[aob + row * 64 + pc * 8], Ab + (size_t)row * KT + ko + sc * 8);
            }
#pragma unroll
            for (int it = 0; it < 4; it++) {
                int row = it * 16 + sr;
                int pc = sc ^ (row & 7);
                cp16(&Bs[bob + row * 64 + pc * 8], Wb + (size_t)row * KT + ko + sc * 8);
            }
            cp_commit();
        }

        const __nv_bfloat16* sA = As + cur * 128 * 64;
        const __nv_bfloat16* sB = Bs + cur * 64 * 64;
#pragma unroll
        for (int ks = 0; ks < 4; ks++) {
            uint32_t af[4][4], bf[2][4];
#pragma unroll
            for (int mt = 0; mt < 4; mt++) {
                int row = wM * 64 + mt * 16 + aRowOff + l7;
                int ch = ks * 2 + aChOff;
                ldsm4(af[mt], sA + row * 64 + ((ch ^ (row & 7)) << 3));
            }
#pragma unroll
            for (int ntp = 0; ntp < 2; ntp++) {
                int row = wN * 32 + ntp * 16 + bRowOff + l7;
                int ch = ks * 2 + bChOff;
                ldsm4(bf[ntp], sB + row * 64 + ((ch ^ (row & 7)) << 3));
            }
#pragma unroll
            for (int mt = 0; mt < 4; mt++)
#pragma unroll
                for (int nt = 0; nt < 4; nt++)
                    mma_bf16(acc[mt][nt], af[mt], &bf[nt >> 1][(nt & 1) * 2]);
        }

        cur ^= 1;
    }

    // peeled final tile: runtime ks bound
    {
        cp_wait<0>();
        __syncthreads();
        const __nv_bfloat16* sA = As + cur * 128 * 64;
        const __nv_bfloat16* sB = Bs + cur * 64 * 64;
#pragma unroll 1
        for (int ks = 0; ks < ksTail; ks++) {
            uint32_t af[4][4], bf[2][4];
#pragma unroll
            for (int mt = 0; mt < 4; mt++) {
                int row = wM * 64 + mt * 16 + aRowOff + l7;
                int ch = ks * 2 + aChOff;
                ldsm4(af[mt], sA + row * 64 + ((ch ^ (row & 7)) << 3));
            }
#pragma unroll
            for (int ntp = 0; ntp < 2; ntp++) {
                int row = wN * 32 + ntp * 16 + bRowOff + l7;
                int ch = ks * 2 + bChOff;
                ldsm4(bf[ntp], sB + row * 64 + ((ch ^ (row & 7)) << 3));
            }
#pragma unroll
            for (int mt = 0; mt < 4; mt++)
#pragma unroll
                for (int nt = 0; nt < 4; nt++)
                    mma_bf16(acc[mt][nt], af[mt], &bf[nt >> 1][(nt & 1) * 2]);
        }
    }

    if (EPI == 0) {
#pragma unroll
        for (int mt = 0; mt < 4; mt++)
#pragma unroll
            for (int hh = 0; hh < 2; hh++) {
                int r = rb + wM * 64 + mt * 16 + hh * 8 + g;
#pragma unroll
                for (int nt = 0; nt < 4; nt++) {
                    int cn = cb + wN * 32 + nt * 8 + 2 * q;
                    float v0 = fmaxf(acc[mt][nt][hh * 2 + 0] + __ldg(&bias[cn]), 0.f);
                    float v1 = fmaxf(acc[mt][nt][hh * 2 + 1] + __ldg(&bias[cn + 1]), 0.f);
                    *(__nv_bfloat162*)(outb + (size_t)r * N + cn) = __floats2bfloat162_rn(v0, v1);
                }
            }
    } else {
        const float CNORM = 2.3052328943245633f;  // 0.5*ln(2pi) + ln(4)
        const int ii = (cb + wN * 32) >> 5;
#pragma unroll
        for (int mt = 0; mt < 4; mt++)
#pragma unroll
            for (int hh = 0; hh < 2; hh++) {
                int r = rb + wM * 64 + mt * 16 + hh * 8 + g;
                float xv = xin[(size_t)r * II + ii];
#pragma unroll
                for (int nt = 0; nt < 2; nt++) {
                    int colm = cb + wN * 32 + nt * 8 + 2 * q;
                    float lp[2];
#pragma unroll
                    for (int e = 0; e < 2; e++) {
                        float mu = acc[mt][nt][hh * 2 + e] + bias[colm + e];
                        float al = acc[mt][nt + 2][hh * 2 + e] + bias[colm + 16 + e];
                        float t = (xv - mu) * __expf(-al);
                        lp[e] = -0.5f * t * t - al - CNORM;
                    }
                    int a = nt * 8 + 2 * q;
                    *(float2*)(outf + ((size_t)ii * BB + r) * 16 + a) = make_float2(lp[0], lp[1]);
                }
            }
    }
}

// ---------------------------------------------------------------------------
__device__ __forceinline__ float max16(const float* v) {
    float m = v[0];
#pragma unroll
    for (int i = 1; i < 16; i++) m = fmaxf(m, v[i]);
    return m;
}

__device__ __forceinline__ void load16(float* d, const float* src) {
    const float4* p = (const float4*)src;
    float4 v0 = p[0], v1 = p[1], v2 = p[2], v3 = p[3];
    d[0] = v0.x; d[1] = v0.y; d[2] = v0.z;  d[3] = v0.w;
    d[4] = v1.x; d[5] = v1.y; d[6] = v1.z;  d[7] = v1.w;
    d[8] = v2.x; d[9] = v2.y; d[10] = v2.z; d[11] = v2.w;
    d[12] = v3.x; d[13] = v3.y; d[14] = v3.z; d[15] = v3.w;
}

__device__ __forceinline__ void matmul44(float* Mn, const float* M, const float* E) {
#pragma unroll
    for (int r = 0; r < 4; r++)
#pragma unroll
        for (int j = 0; j < 4; j++) {
            float s = M[r * 4 + 0] * E[j];
            s = fmaf(M[r * 4 + 1], E[4 + j], s);
            s = fmaf(M[r * 4 + 2], E[8 + j], s);
            s = fmaf(M[r * 4 + 3], E[12 + j], s);
            Mn[r * 4 + j] = s;
        }
}

__global__ __launch_bounds__(256) void chainA_k()
{
    const int b = blockIdx.x * 256 + threadIdx.x;
    const int c = blockIdx.y;
    const int i0 = 1 + c * CHLEN;

    float M[16], S;
    {
        float lp[16];
        load16(lp, g_lp + ((size_t)i0 * BB + b) * 16);
        float mx = max16(lp);
        S = mx;
#pragma unroll
        for (int a = 0; a < 16; a++) M[a] = __expf(lp[a] - mx);
    }
#pragma unroll
    for (int s = 1; s < CHLEN; s++) {
        float lp[16];
        load16(lp, g_lp + ((size_t)(i0 + s) * BB + b) * 16);
        float mx = max16(lp);
        float E[16];
#pragma unroll
        for (int a = 0; a < 16; a++) E[a] = __expf(lp[a] - mx);
        float Mn[16];
        matmul44(Mn, M, E);
        float nm = fmaxf(max16(Mn), 1e-30f);
        float inv = 1.0f / nm;
#pragma unroll
        for (int a = 0; a < 16; a++) M[a] = Mn[a] * inv;
        S += mx + __logf(nm);
    }
    float4* o = (float4*)(g_cm + ((size_t)c * BB + b) * 16);
    o[0] = make_float4(M[0], M[1], M[2], M[3]);
    o[1] = make_float4(M[4], M[5], M[6], M[7]);
    o[2] = make_float4(M[8], M[9], M[10], M[11]);
    o[3] = make_float4(M[12], M[13], M[14], M[15]);
    g_cs[c * BB + b] = S;
}

__global__ __launch_bounds__(256) void chainB_k(float* __restrict__ out)
{
    const int b = blockIdx.x * 256 + threadIdx.x;

    float M[16];
    load16(M, g_cm + (size_t)b * 16);
    float S = g_cs[b];

    for (int c = 1; c < NCHUNK; c++) {
        float E[16];
        load16(E, g_cm + ((size_t)c * BB + b) * 16);
        float Mn[16];
        matmul44(Mn, M, E);
        float nm = fmaxf(max16(Mn), 1e-30f);
        float inv = 1.0f / nm;
#pragma unroll
        for (int a = 0; a < 16; a++) M[a] = Mn[a] * inv;
        S += g_cs[c * BB + b] + __logf(nm);
    }

    const float* lp0 = g_lp + (size_t)b * 16;
    const float* lpL = g_lp + ((size_t)127 * BB + b) * 16;
    float f[4] = {lp0[0], lp0[1], lp0[2], lp0[3]};
    float l[4] = {lpL[0], lpL[4], lpL[8], lpL[12]};
    float fm = fmaxf(fmaxf(f[0], f[1]), fmaxf(f[2], f[3]));
    float lm = fmaxf(fmaxf(l[0], l[1]), fmaxf(l[2], l[3]));
    float ef[4], el[4];
#pragma unroll
    for (int i = 0; i < 4; i++) { ef[i] = __expf(f[i] - fm); el[i] = __expf(l[i] - lm); }
    float acc = 0.f;
#pragma unroll
    for (int i = 0; i < 4; i++) {
        float rs = M[i * 4 + 0] * el[0];
        rs = fmaf(M[i * 4 + 1], el[1], rs);
        rs = fmaf(M[i * 4 + 2], el[2], rs);
        rs = fmaf(M[i * 4 + 3], el[3], rs);
        acc = fmaf(ef[i], rs, acc);
    }
    out[b] = S + fm + lm + __logf(acc);
}

// ---------------------------------------------------------------------------
extern "C" void kernel_launch(void* const* d_in, const int* in_sizes, int n_in,
                              void* d_out, int out_size)
{
    const float* x  = (const float*)d_in[0];
    const float* W0 = (const float*)d_in[1];
    const float* b0 = (const float*)d_in[2];
    const float* W1 = (const float*)d_in[3];
    const float* b1 = (const float*)d_in[4];
    const float* W2 = (const float*)d_in[5];
    const float* b2 = (const float*)d_in[6];
    const float* W3 = (const float*)d_in[7];
    const float* b3 = (const float*)d_in[8];

    __nv_bfloat16 *xb, *W0b, *W1b, *W2b, *W3b, *h0, *h1;
    float *lp, *b0p, *b1p, *b2p;
    cudaGetSymbolAddress((void**)&xb, g_xb);
    cudaGetSymbolAddress((void**)&W0b, g_W0b);
    cudaGetSymbolAddress((void**)&W1b, g_W1b);
    cudaGetSymbolAddress((void**)&W2b, g_W2b);
    cudaGetSymbolAddress((void**)&W3b, g_W3b);
    cudaGetSymbolAddress((void**)&h0, g_h0);
    cudaGetSymbolAddress((void**)&h1, g_h1);
    cudaGetSymbolAddress((void**)&lp, g_lp);
    cudaGetSymbolAddress((void**)&b0p, g_b0p);
    cudaGetSymbolAddress((void**)&b1p, g_b1p);
    cudaGetSymbolAddress((void**)&b2p, g_b2p);

    // one-time handles (created on the first, uncaptured call; identical
    // work is enqueued on every call)
    static cudaStream_t s2 = nullptr;
    static cudaEvent_t evRoot = nullptr, ev1 = nullptr, ev2 = nullptr, ev3 = nullptr;
    if (!s2) {
        cudaStreamCreateWithFlags(&s2, cudaStreamNonBlocking);
        cudaEventCreateWithFlags(&evRoot, cudaEventDisableTiming);
        cudaEventCreateWithFlags(&ev1, cudaEventDisableTiming);
        cudaEventCreateWithFlags(&ev2, cudaEventDisableTiming);
        cudaEventCreateWithFlags(&ev3, cudaEventDisableTiming);
    }

    // 2 stages x (A 16KB + B 8KB) = 48KB
    const int SMEM = 2 * (128 * 64 + 64 * 64) * (int)sizeof(__nv_bfloat16);
    cudaFuncSetAttribute(gemm_bf16_k<0, 0, II>, cudaFuncAttributeMaxDynamicSharedMemorySize, SMEM);
    cudaFuncSetAttribute(gemm_bf16_k<1, 0, HH>, cudaFuncAttributeMaxDynamicSharedMemorySize, SMEM);
    cudaFuncSetAttribute(gemm_bf16_k<2, 1, HH>, cudaFuncAttributeMaxDynamicSharedMemorySize, SMEM);

    // fork: weight conversions W1/W2/W3 on side stream, overlapped with GEMMs
    cudaEventRecord(evRoot, 0);
    cudaStreamWaitEvent(s2, evRoot, 0);
    pro_w_k<1><<<HH, 256, 0, s2>>>(W1, W1b);
    cudaEventRecord(ev1, s2);
    pro_w_k<1><<<HH, 256, 0, s2>>>(W2, W2b);
    cudaEventRecord(ev2, s2);
    pro_w_k<2><<<N3, 256, 0, s2>>>(W3, W3b);
    cudaEventRecord(ev3, s2);

    // main stream: x+W0+biases, then GEMMs joining weight events just-in-time
    pro_xw0_k<<<1304, 256>>>(x, W0, b0, b1, b2);
    gemm_bf16_k<0, 0, II><<<dim3(BB / 128, HH / 64), 128, SMEM>>>(xb, W0b, b0p, nullptr, h0, nullptr, HH);
    cudaStreamWaitEvent(0, ev1, 0);
    gemm_bf16_k<1, 0, HH><<<dim3(BB / 128, HH / 64), 128, SMEM>>>(h0, W1b, b1p, nullptr, h1, nullptr, HH);
    cudaStreamWaitEvent(0, ev2, 0);
    gemm_bf16_k<1, 0, HH><<<dim3(BB / 128, HH / 64), 128, SMEM>>>(h1, W2b, b2p, nullptr, h0, nullptr, HH);
    cudaStreamWaitEvent(0, ev3, 0);
    gemm_bf16_k<2, 1, HH><<<dim3(BB / 128, N3 / 64), 128, SMEM>>>(h0, W3b, b3, lp, nullptr, x, N3);

    // chain
    chainA_k<<<dim3(BB / 256, NCHUNK), 256>>>();
    chainB_k<<<BB / 256, 256>>>((float*)d_out);
}